// round 3
// baseline (speedup 1.0000x reference)
#include <cuda_runtime.h>
#include <cuda_bf16.h>
#include <math.h>
#include <float.h>

// ---------------------------------------------------------------------------
// Problem constants
// ---------------------------------------------------------------------------
#define BSZ       4
#define SEQ       2048
#define DIM       2048
#define NHEADS    16
#define NKVHEADS  4
#define HEADDIM   128
#define KVDIM     (NKVHEADS * HEADDIM)   // 512
#define ROWS      (BSZ * SEQ)            // 8192
#define HALFHD    (HEADDIM / 2)          // 64

// ---------------------------------------------------------------------------
// Scratch (device globals — no allocations allowed)
// ---------------------------------------------------------------------------
__device__ float g_q[(size_t)ROWS * DIM];     // [b,s,h,d]  64 MB
__device__ float g_k[(size_t)ROWS * KVDIM];   // [b,s,kvh,d] 16 MB
__device__ float g_v[(size_t)ROWS * KVDIM];   // 16 MB
__device__ float g_y[(size_t)ROWS * DIM];     // attention out [b,s,h,d] 64 MB
__device__ float g_cos[SEQ * HALFHD];
__device__ float g_sin[SEQ * HALFHD];

// ---------------------------------------------------------------------------
// SGEMM: C[M,N] = A[M,K] * B[N,K]^T (both K-contiguous), tiles 128x128x8,
// 256 threads, 8x8 microtile, DOUBLE-BUFFERED smem:
//   - next tile's LDG issues before the FFMA block (latency hidden)
//   - STS targets the idle buffer -> ONE __syncthreads per K-iteration
// ---------------------------------------------------------------------------
__global__ void __launch_bounds__(256)
sgemm_nt(const float* __restrict__ A, const float* __restrict__ B,
         float* __restrict__ C, int M, int N, int K)
{
    __shared__ float As[2][8][128];
    __shared__ float Bs[2][8][128];

    const int tid = threadIdx.x;
    const int tx = tid & 15;
    const int ty = tid >> 4;
    const int m0 = blockIdx.y * 128;
    const int n0 = blockIdx.x * 128;

    const int lr = tid >> 1;          // 0..127
    const int lk = (tid & 1) * 4;     // 0 or 4

    const float* Ap = A + (size_t)(m0 + lr) * K + lk;
    const float* Bp = B + (size_t)(n0 + lr) * K + lk;

    float c[8][8];
#pragma unroll
    for (int i = 0; i < 8; i++)
#pragma unroll
        for (int j = 0; j < 8; j++) c[i][j] = 0.f;

    const int niter = K >> 3;

    // Prologue: tile 0 -> buffer 0
    float4 av = *(const float4*)(Ap);
    float4 bv = *(const float4*)(Bp);
    As[0][lk + 0][lr] = av.x; As[0][lk + 1][lr] = av.y;
    As[0][lk + 2][lr] = av.z; As[0][lk + 3][lr] = av.w;
    Bs[0][lk + 0][lr] = bv.x; Bs[0][lk + 1][lr] = bv.y;
    Bs[0][lk + 2][lr] = bv.z; Bs[0][lk + 3][lr] = bv.w;
    __syncthreads();

    int cur = 0;
    for (int it = 0; it < niter; it++) {
        // Prefetch next tile into registers (overlaps with FFMA below)
        if (it + 1 < niter) {
            av = *(const float4*)(Ap + (it + 1) * 8);
            bv = *(const float4*)(Bp + (it + 1) * 8);
        }

        // Compute on current buffer
#pragma unroll
        for (int kt = 0; kt < 8; kt++) {
            float a[8], b[8];
            *(float4*)(a)     = *(const float4*)&As[cur][kt][ty * 8];
            *(float4*)(a + 4) = *(const float4*)&As[cur][kt][ty * 8 + 4];
            *(float4*)(b)     = *(const float4*)&Bs[cur][kt][tx * 8];
            *(float4*)(b + 4) = *(const float4*)&Bs[cur][kt][tx * 8 + 4];
#pragma unroll
            for (int i = 0; i < 8; i++)
#pragma unroll
                for (int j = 0; j < 8; j++)
                    c[i][j] += a[i] * b[j];
        }

        // Store prefetched tile to the idle buffer; single barrier
        if (it + 1 < niter) {
            const int nxt = cur ^ 1;
            As[nxt][lk + 0][lr] = av.x; As[nxt][lk + 1][lr] = av.y;
            As[nxt][lk + 2][lr] = av.z; As[nxt][lk + 3][lr] = av.w;
            Bs[nxt][lk + 0][lr] = bv.x; Bs[nxt][lk + 1][lr] = bv.y;
            Bs[nxt][lk + 2][lr] = bv.z; Bs[nxt][lk + 3][lr] = bv.w;
            __syncthreads();
            cur = nxt;
        }
    }

#pragma unroll
    for (int i = 0; i < 8; i++) {
        float* Cp = C + (size_t)(m0 + ty * 8 + i) * N + n0 + tx * 8;
        *(float4*)(Cp)     = make_float4(c[i][0], c[i][1], c[i][2], c[i][3]);
        *(float4*)(Cp + 4) = make_float4(c[i][4], c[i][5], c[i][6], c[i][7]);
    }
}

// ---------------------------------------------------------------------------
// RoPE table: mimic reference fp32 rounding chain:
//   inv_freq = fp32(10000^(-i/64)); freq = fp32(s * inv_freq); cos/sin in f64
// ---------------------------------------------------------------------------
__global__ void __launch_bounds__(256)
rope_table_kernel()
{
    int idx = blockIdx.x * blockDim.x + threadIdx.x;   // 0 .. SEQ*64-1
    if (idx >= SEQ * HALFHD) return;
    int s = idx >> 6;
    int i = idx & 63;
    float invf = (float)pow(10000.0, -(double)i / 64.0);
    float fr = (float)s * invf;
    g_cos[idx] = (float)cos((double)fr);
    g_sin[idx] = (float)sin((double)fr);
}

// ---------------------------------------------------------------------------
// Fused per-head RMSnorm + RoPE (+ q_gain for q heads). One warp per head-row.
// Lane l owns dims {l, l+32, l+64, l+96}: rotation pairs (l,l+64),(l+32,l+96)
// are lane-local.
// ---------------------------------------------------------------------------
__global__ void __launch_bounds__(256)
norm_rope_kernel(const float* __restrict__ q_gain)
{
    const int gw = blockIdx.x * 8 + (threadIdx.x >> 5);  // global warp id
    const int lane = threadIdx.x & 31;
    const int row = gw / (NHEADS + NKVHEADS);            // b*SEQ + s
    const int slot = gw % (NHEADS + NKVHEADS);           // 0..15 q, 16..19 k
    const int s = row & (SEQ - 1);

    const bool is_q = slot < NHEADS;
    float* ptr = is_q ? (g_q + (size_t)row * DIM + slot * HEADDIM)
                      : (g_k + (size_t)row * KVDIM + (slot - NHEADS) * HEADDIM);

    float v0 = ptr[lane];
    float v1 = ptr[lane + 32];
    float v2 = ptr[lane + 64];
    float v3 = ptr[lane + 96];

    float ss = v0 * v0 + v1 * v1 + v2 * v2 + v3 * v3;
#pragma unroll
    for (int o = 16; o > 0; o >>= 1)
        ss += __shfl_xor_sync(0xffffffffu, ss, o);

    const float sc = rsqrtf(ss * (1.0f / 128.0f) + 1.1920929e-7f);
    v0 *= sc; v1 *= sc; v2 *= sc; v3 *= sc;

    const float c0 = g_cos[s * HALFHD + lane];
    const float s0 = g_sin[s * HALFHD + lane];
    const float c1 = g_cos[s * HALFHD + lane + 32];
    const float s1 = g_sin[s * HALFHD + lane + 32];

    float o0 =  v0 * c0 + v2 * s0;
    float o2 = -v0 * s0 + v2 * c0;
    float o1 =  v1 * c1 + v3 * s1;
    float o3 = -v1 * s1 + v3 * c1;

    if (is_q) {
        const float g = q_gain[slot];
        o0 *= g; o1 *= g; o2 *= g; o3 *= g;
    }

    ptr[lane]      = o0;
    ptr[lane + 32] = o1;
    ptr[lane + 64] = o2;
    ptr[lane + 96] = o3;
}

// ---------------------------------------------------------------------------
// Flash attention (causal, GQA rep=4). BM=BN=64, 256 threads as 16x16.
// Thread (ty,tx): score rows 4ty..4ty+3, score cols 4tx..4tx+3,
//                 output dims 8tx..8tx+7.
// Smem: sqT[128][64], skT[128][64], sv[64][128], sp[64][68].
// P-tile rows are warp-private (rows 8w..8w+7 <-> warp w) -> __syncwarp only.
// K/V global loads are issued into registers BEFORE the consumer-wait
// barrier so their latency overlaps the barrier (1 CTA/SM here -> nothing
// else hides it).
// ---------------------------------------------------------------------------
#define FA_SQ  0
#define FA_SK  (128 * 64)
#define FA_SV  (FA_SK + 128 * 64)
#define FA_SP  (FA_SV + 64 * 128)
#define FA_SMEM_FLOATS (FA_SP + 64 * 68)
#define FA_SMEM_BYTES  (FA_SMEM_FLOATS * 4)

__global__ void __launch_bounds__(256)
flash_attn_kernel()
{
    extern __shared__ float smem[];
    float* sq = smem + FA_SQ;
    float* sk = smem + FA_SK;
    float* sv = smem + FA_SV;
    float* sp = smem + FA_SP;

    const int tid = threadIdx.x;
    const int tx = tid & 15;
    const int ty = tid >> 4;

    const int bx = blockIdx.x;
    const int qt = 31 - (bx & 31);        // q tile index, descending work order
    const int bh = bx >> 5;
    const int b = bh >> 4;
    const int h = bh & 15;
    const int kvh = h >> 2;
    const int q0 = qt * 64;

    const float scale = 1.0f / sqrtf(128.0f);

    // Load Q tile (scaled), transposed into sqT[d][m]
    {
        const float* qbase = g_q + ((size_t)(b * SEQ + q0)) * DIM + h * HEADDIM;
#pragma unroll
        for (int it = 0; it < 8; it++) {
            int i = tid + it * 256;          // 0..2047
            int r = i >> 5;
            int dc = (i & 31) * 4;
            float4 qv = *(const float4*)(qbase + (size_t)r * DIM + dc);
            sq[(dc + 0) * 64 + r] = qv.x * scale;
            sq[(dc + 1) * 64 + r] = qv.y * scale;
            sq[(dc + 2) * 64 + r] = qv.z * scale;
            sq[(dc + 3) * 64 + r] = qv.w * scale;
        }
    }

    float m[4], l[4], o[4][8];
#pragma unroll
    for (int i = 0; i < 4; i++) { m[i] = -INFINITY; l[i] = 0.f; }
#pragma unroll
    for (int i = 0; i < 4; i++)
#pragma unroll
        for (int j = 0; j < 8; j++) o[i][j] = 0.f;

    // per-thread chunk coords for K/V tile loads
    const int lr8 = tid >> 5;             // base row 0..7 (+8*it)
    const int ldc = (tid & 31) * 4;       // d column 0..124

    for (int jt = 0; jt <= qt; jt++) {
        const int t0 = jt * 64;

        // Issue K/V global loads BEFORE the barrier (hide latency behind it)
        float4 kreg[8], vreg[8];
        {
            const float* kbase = g_k + ((size_t)(b * SEQ + t0)) * KVDIM + kvh * HEADDIM;
            const float* vbase = g_v + ((size_t)(b * SEQ + t0)) * KVDIM + kvh * HEADDIM;
#pragma unroll
            for (int it = 0; it < 8; it++) {
                int r = lr8 + it * 8;
                kreg[it] = *(const float4*)(kbase + (size_t)r * KVDIM + ldc);
                vreg[it] = *(const float4*)(vbase + (size_t)r * KVDIM + ldc);
            }
        }

        __syncthreads();   // prior-iter smem reads complete (also covers Q stores)

#pragma unroll
        for (int it = 0; it < 8; it++) {
            int r = lr8 + it * 8;
            sk[(ldc + 0) * 64 + r] = kreg[it].x;
            sk[(ldc + 1) * 64 + r] = kreg[it].y;
            sk[(ldc + 2) * 64 + r] = kreg[it].z;
            sk[(ldc + 3) * 64 + r] = kreg[it].w;
            *(float4*)&sv[r * 128 + ldc] = vreg[it];
        }
        __syncthreads();

        // S = Q * K^T  (64x64 tile, 4x4 per thread)
        float sacc[4][4];
#pragma unroll
        for (int i = 0; i < 4; i++)
#pragma unroll
            for (int j = 0; j < 4; j++) sacc[i][j] = 0.f;

#pragma unroll 8
        for (int d = 0; d < 128; d++) {
            float a[4], bb[4];
            *(float4*)a  = *(const float4*)&sq[d * 64 + ty * 4];
            *(float4*)bb = *(const float4*)&sk[d * 64 + tx * 4];
#pragma unroll
            for (int i = 0; i < 4; i++)
#pragma unroll
                for (int j = 0; j < 4; j++)
                    sacc[i][j] += a[i] * bb[j];
        }

        // Causal mask on the diagonal tile
        if (jt == qt) {
#pragma unroll
            for (int i = 0; i < 4; i++)
#pragma unroll
                for (int j = 0; j < 4; j++)
                    if (tx * 4 + j > ty * 4 + i) sacc[i][j] = -INFINITY;
        }

        // Online softmax (row stats shared across the 16 tx lanes of a ty group)
        float tm[4], rs[4], f[4];
#pragma unroll
        for (int i = 0; i < 4; i++) {
            tm[i] = fmaxf(fmaxf(sacc[i][0], sacc[i][1]),
                          fmaxf(sacc[i][2], sacc[i][3]));
        }
#pragma unroll
        for (int o16 = 8; o16 > 0; o16 >>= 1)
#pragma unroll
            for (int i = 0; i < 4; i++)
                tm[i] = fmaxf(tm[i], __shfl_xor_sync(0xffffffffu, tm[i], o16));

        float pv[4][4];
#pragma unroll
        for (int i = 0; i < 4; i++) {
            float mn = fmaxf(m[i], tm[i]);
            f[i] = expf(m[i] - mn);
            m[i] = mn;
            float r = 0.f;
#pragma unroll
            for (int j = 0; j < 4; j++) {
                float p = expf(sacc[i][j] - mn);
                pv[i][j] = p;
                r += p;
            }
            rs[i] = r;
        }
#pragma unroll
        for (int o16 = 8; o16 > 0; o16 >>= 1)
#pragma unroll
            for (int i = 0; i < 4; i++)
                rs[i] += __shfl_xor_sync(0xffffffffu, rs[i], o16);
#pragma unroll
        for (int i = 0; i < 4; i++) {
            l[i] = l[i] * f[i] + rs[i];
#pragma unroll
            for (int j = 0; j < 8; j++) o[i][j] *= f[i];
        }

        // P tile to smem (warp-private rows), then O += P * V
        __syncwarp();
#pragma unroll
        for (int i = 0; i < 4; i++)
            *(float4*)&sp[(ty * 4 + i) * 68 + tx * 4] =
                make_float4(pv[i][0], pv[i][1], pv[i][2], pv[i][3]);
        __syncwarp();

#pragma unroll 8
        for (int t = 0; t < 64; t++) {
            float pr[4];
#pragma unroll
            for (int i = 0; i < 4; i++) pr[i] = sp[(ty * 4 + i) * 68 + t];
            float4 va = *(const float4*)&sv[t * 128 + tx * 8];
            float4 vb = *(const float4*)&sv[t * 128 + tx * 8 + 4];
            float vf[8] = {va.x, va.y, va.z, va.w, vb.x, vb.y, vb.z, vb.w};
#pragma unroll
            for (int i = 0; i < 4; i++)
#pragma unroll
                for (int j = 0; j < 8; j++)
                    o[i][j] += pr[i] * vf[j];
        }
    }

    // Epilogue: y[b, q0+r, h*128 + d] = o / l
#pragma unroll
    for (int i = 0; i < 4; i++) {
        const float inv = 1.0f / l[i];
        float* yp = g_y + ((size_t)(b * SEQ + q0 + ty * 4 + i)) * DIM
                  + h * HEADDIM + tx * 8;
        *(float4*)(yp)     = make_float4(o[i][0] * inv, o[i][1] * inv,
                                         o[i][2] * inv, o[i][3] * inv);
        *(float4*)(yp + 4) = make_float4(o[i][4] * inv, o[i][5] * inv,
                                         o[i][6] * inv, o[i][7] * inv);
    }
}

// ---------------------------------------------------------------------------
// Launch
// ---------------------------------------------------------------------------
extern "C" void kernel_launch(void* const* d_in, const int* in_sizes, int n_in,
                              void* d_out, int out_size)
{
    const float* x      = (const float*)d_in[0];
    const float* Wq     = (const float*)d_in[1];
    const float* Wk     = (const float*)d_in[2];
    const float* Wv     = (const float*)d_in[3];
    const float* Wo     = (const float*)d_in[4];
    const float* q_gain = (const float*)d_in[5];
    float* out = (float*)d_out;

    // One-time, non-capturable setup done on the first (correctness) call;
    // captured replays see only kernel launches.
    static float *qp = nullptr, *kp = nullptr, *vp = nullptr, *yp = nullptr;
    static int initialized = 0;
    if (!initialized) {
        cudaGetSymbolAddress((void**)&qp, g_q);
        cudaGetSymbolAddress((void**)&kp, g_k);
        cudaGetSymbolAddress((void**)&vp, g_v);
        cudaGetSymbolAddress((void**)&yp, g_y);
        cudaFuncSetAttribute(flash_attn_kernel,
                             cudaFuncAttributeMaxDynamicSharedMemorySize,
                             FA_SMEM_BYTES);
        initialized = 1;
    }

    // QKV projections
    sgemm_nt<<<dim3(DIM / 128, ROWS / 128), 256>>>(x, Wq, qp, ROWS, DIM, DIM);
    sgemm_nt<<<dim3(KVDIM / 128, ROWS / 128), 256>>>(x, Wk, kp, ROWS, KVDIM, DIM);
    sgemm_nt<<<dim3(KVDIM / 128, ROWS / 128), 256>>>(x, Wv, vp, ROWS, KVDIM, DIM);

    // RoPE table + fused RMSnorm/RoPE/gain
    rope_table_kernel<<<(SEQ * HALFHD + 255) / 256, 256>>>();
    {
        const int total_warps = ROWS * (NHEADS + NKVHEADS);   // 163840
        norm_rope_kernel<<<total_warps / 8, 256>>>(q_gain);
    }

    // Flash attention
    flash_attn_kernel<<<BSZ * NHEADS * (SEQ / 64), 256, FA_SMEM_BYTES>>>();

    // Output projection
    sgemm_nt<<<dim3(DIM / 128, ROWS / 128), 256>>>(yp, Wo, out, ROWS, DIM, DIM);
}